// round 7
// baseline (speedup 1.0000x reference)
#include <cuda_runtime.h>
#include <cuda_fp16.h>
#include <cstdint>

#define TEMP 30.0f

// ---------------- static device scratch ----------------
// aggregated fp16 weights: [b][coH(2)][chunk(16)][tap(9)][coL(128)][ci(16)]
__device__ __half g_w16[(size_t)32 * 2 * 16 * 9 * 128 * 16];
// transposed fp16 x: [b][f(64)][t(64)][ci(256)]
__device__ __half g_xT[(size_t)32 * 64 * 64 * 256];

// ---------------- helpers ----------------
__device__ __forceinline__ uint32_t smem_u32(const void* p) {
    uint32_t a;
    asm("{ .reg .u64 t; cvta.to.shared.u64 t, %1; cvt.u32.u64 %0, t; }" : "=r"(a) : "l"(p));
    return a;
}
__device__ __forceinline__ void cp16(uint32_t saddr, const void* g) {
    asm volatile("cp.async.cg.shared.global [%0], [%1], 16;" :: "r"(saddr), "l"(g));
}
__device__ __forceinline__ void ldsm_x4(uint32_t addr, uint32_t* r) {
    asm volatile("ldmatrix.sync.aligned.m8n8.x4.shared.b16 {%0,%1,%2,%3}, [%4];"
                 : "=r"(r[0]), "=r"(r[1]), "=r"(r[2]), "=r"(r[3]) : "r"(addr));
}
__device__ __forceinline__ void mma16816(float* d, const uint32_t* a,
                                         const uint32_t* b) {
    asm volatile(
        "mma.sync.aligned.m16n8k16.row.col.f32.f16.f16.f32 "
        "{%0,%1,%2,%3}, {%4,%5,%6,%7}, {%8,%9}, {%0,%1,%2,%3};"
        : "+f"(d[0]), "+f"(d[1]), "+f"(d[2]), "+f"(d[3])
        : "r"(a[0]), "r"(a[1]), "r"(a[2]), "r"(a[3]), "r"(b[0]), "r"(b[1]));
}

// ---------------------------------------------------------------------------
// Kernel 1: aggregate expert weights -> fp16 tiled layout (attention fused).
// Each block spans exactly one b (blockIdx.x>>5).
// ---------------------------------------------------------------------------
__global__ void agg16_kernel(const float* __restrict__ w,
                             const float* __restrict__ g,
                             const float* __restrict__ dw,
                             const float* __restrict__ db) {
    __shared__ float sp[4][4];
    __shared__ float s_att[4];
    const int b = blockIdx.x >> 5;
    const int tid = threadIdx.x;
    if (tid < 128) {
        int k = tid & 3, wrp = tid >> 5, lane = tid & 31;
        const float* gb = g + b * 256;
        float s = 0.f;
        for (int c = tid >> 2; c < 256; c += 32) s += gb[c] * dw[c * 4 + k];
        s += __shfl_xor_sync(~0u, s, 4);
        s += __shfl_xor_sync(~0u, s, 8);
        s += __shfl_xor_sync(~0u, s, 16);
        if (lane < 4) sp[wrp][k] = s;
    }
    __syncthreads();
    if (tid < 4) {
        int k = tid;
        float t = (sp[0][k] + sp[1][k] + sp[2][k] + sp[3][k] + db[k]) * (1.f / TEMP);
        float m = t;
        m = fmaxf(m, __shfl_xor_sync(0xF, m, 1));
        m = fmaxf(m, __shfl_xor_sync(0xF, m, 2));
        float e = expf(t - m);
        float su = e;
        su += __shfl_xor_sync(0xF, su, 1);
        su += __shfl_xor_sync(0xF, su, 2);
        s_att[k] = e / su;
    }
    __syncthreads();

    const int idx = blockIdx.x * 256 + tid;
    const int ci8 = idx & 31;
    const int co  = (idx >> 5) & 255;
    float acc[72];
#pragma unroll
    for (int e = 0; e < 72; ++e) acc[e] = 0.f;
#pragma unroll
    for (int k = 0; k < 4; ++k) {
        float a = s_att[k];
        const float4* wp =
            (const float4*)(w + (((size_t)k * 256 + co) * 256 + ci8 * 8) * 9);
#pragma unroll
        for (int q = 0; q < 18; ++q) {
            float4 f = wp[q];
            acc[q * 4 + 0] += a * f.x;
            acc[q * 4 + 1] += a * f.y;
            acc[q * 4 + 2] += a * f.z;
            acc[q * 4 + 3] += a * f.w;
        }
    }
    int coH = co >> 7, coL = co & 127, ch = ci8 >> 1, half8 = ci8 & 1;
#pragma unroll
    for (int kk = 0; kk < 9; ++kk) {
        __half2 h[4];
#pragma unroll
        for (int p = 0; p < 4; ++p)
            h[p] = __halves2half2(__float2half_rn(acc[(2 * p) * 9 + kk]),
                                  __float2half_rn(acc[(2 * p + 1) * 9 + kk]));
        __half* dst = g_w16 +
            (((((size_t)b * 2 + coH) * 16 + ch) * 9 + kk) * 128 + coL) * 16 + half8 * 8;
        *(uint4*)dst = *(uint4*)h;
    }
}

// ---------------------------------------------------------------------------
// Kernel 2: x -> fp16 transposed [b][f][t][ci]
// ---------------------------------------------------------------------------
__global__ void xT_kernel(const float* __restrict__ x) {
    __shared__ __half s[64][272];
    int f = blockIdx.x, b = blockIdx.y, tid = threadIdx.x;
    const float* xb = x + ((size_t)b * 256 * 4096 + (size_t)f * 64);
    for (int i = tid; i < 256 * 64; i += 256) {
        int ci = i >> 6, t = i & 63;
        s[t][ci] = __float2half_rn(xb[(size_t)ci * 4096 + t]);
    }
    __syncthreads();
    __half* dst = g_xT + ((size_t)(b * 64 + f)) * 64 * 256;
    for (int i = tid; i < 64 * 32; i += 256) {
        int t = i >> 5, c8 = (i & 31) * 8;
        *(uint4*)(dst + t * 256 + c8) = *(uint4*)&s[t][c8];
    }
}

// ---------------------------------------------------------------------------
// Kernel 3: conv via mma.sync m16n8k16.
// CTA = (b, coH 128co, 4 fo x 64 t), 512 threads / 16 warps (4 per SMSP).
// Warp tile 32co x 64t x 1fo: wco = wid&3, wfo = wid>>2.
// 16 ci-chunks, 3-stage cp.async pipeline. B rows padded to 48B, halos zero.
// ---------------------------------------------------------------------------
#define STG_A 55296          // 9 taps * 128 co * 48B
#define STG_B 19008          // 6 fi planes * 66 t-rows * 48B
#define NSTG 3
#define B_BASE (NSTG * STG_A)
#define SMEM_CONV (NSTG * STG_A + NSTG * STG_B)   // 222912

__global__ __launch_bounds__(512, 1) void conv_kernel(float* __restrict__ out) {
    extern __shared__ __align__(16) char smem[];
    const int tid = threadIdx.x, wid = tid >> 5, lane = tid & 31;
    const int b = blockIdx.z, coH = blockIdx.y, fo0 = blockIdx.x * 4;
    const int wco = wid & 3, wfo = wid >> 2;
    const uint32_t sb = smem_u32(smem);

    // zero all B stages (halo rows/planes stay zero forever)
    for (int i = tid; i < NSTG * STG_B / 4; i += 512)
        ((uint32_t*)(smem + B_BASE))[i] = 0u;
    __syncthreads();

    const __half* wbase = g_w16 + (((size_t)b * 2 + coH) * 16) * (9 * 128 * 16);

    auto load_stage = [&](int ch) {
        const int slot = ch % NSTG, ci0 = ch * 16;
        const __half* wsrc = wbase + (size_t)ch * (9 * 128 * 16);
        uint32_t ad = sb + slot * STG_A;
        for (int i = tid; i < 2304; i += 512) {
            int rc = i >> 1, q = i & 1;
            cp16(ad + rc * 48 + q * 16, wsrc + (size_t)i * 8);
        }
        uint32_t bd = sb + B_BASE + slot * STG_B;
        for (int i = tid; i < 768; i += 512) {
            int row = i >> 1, q = i & 1;
            int p = row >> 6, t = row & 63;
            int fi = fo0 - 1 + p;
            if ((unsigned)fi < 64u)
                cp16(bd + p * 3168 + (t + 1) * 48 + q * 16,
                     g_xT + (((size_t)(b * 64 + fi)) * 64 + t) * 256 + ci0 + q * 8);
        }
        asm volatile("cp.async.commit_group;" ::: "memory");
    };

    float acc[2][8][4];
#pragma unroll
    for (int m = 0; m < 2; ++m)
#pragma unroll
        for (int n = 0; n < 8; ++n)
#pragma unroll
            for (int e = 0; e < 4; ++e) acc[m][n][e] = 0.f;

    load_stage(0);
    load_stage(1);
    load_stage(2);

    const uint32_t aLane = (lane & 15) * 48 + (lane >> 4) * 16;
    const uint32_t bLane = ((lane & 7) + ((lane & 16) >> 1)) * 48 +
                           ((lane & 8) ? 16u : 0u);

    for (int ch = 0; ch < 16; ++ch) {
        const int slot = ch % NSTG;
        if (ch <= 13)      asm volatile("cp.async.wait_group 2;" ::: "memory");
        else if (ch == 14) asm volatile("cp.async.wait_group 1;" ::: "memory");
        else               asm volatile("cp.async.wait_group 0;" ::: "memory");
        __syncthreads();

        const uint32_t As = sb + slot * STG_A + (wco * 32) * 48 + aLane;
        const uint32_t Bs = sb + B_BASE + slot * STG_B + (wfo * 3168) + bLane;
#pragma unroll
        for (int kh = 0; kh < 3; ++kh) {
#pragma unroll
            for (int kw = 0; kw < 3; ++kw) {
                const int tap = kh * 3 + kw;
                uint32_t a[2][4];
                ldsm_x4(As + tap * 6144, a[0]);
                ldsm_x4(As + tap * 6144 + 768, a[1]);
                uint32_t bf[4][4];
                const uint32_t Bp = Bs + kh * 3168 + kw * 48;
#pragma unroll
                for (int nt = 0; nt < 4; ++nt)
                    ldsm_x4(Bp + nt * 768, bf[nt]);
#pragma unroll
                for (int m = 0; m < 2; ++m)
#pragma unroll
                    for (int nt = 0; nt < 4; ++nt) {
                        mma16816(acc[m][nt * 2],     a[m], bf[nt]);
                        mma16816(acc[m][nt * 2 + 1], a[m], bf[nt] + 2);
                    }
            }
        }
        __syncthreads();
        if (ch + 3 < 16) load_stage(ch + 3);
    }

    // epilogue: direct float2 stores
    const int gRow = lane >> 2, col2 = (lane & 3) * 2;
    const int fo = fo0 + wfo;
#pragma unroll
    for (int m = 0; m < 2; ++m) {
        const int co = coH * 128 + wco * 32 + m * 16 + gRow;
#pragma unroll
        for (int nt = 0; nt < 4; ++nt)
#pragma unroll
            for (int j = 0; j < 2; ++j) {
                const int t = nt * 16 + j * 8 + col2;
                const float* d = acc[m][nt * 2 + j];
                size_t o0 = (((size_t)(b * 256 + co)) * 64 + fo) * 64 + t;
                *(float2*)&out[o0] = make_float2(d[0], d[1]);
                size_t o1 = o0 + 8 * 64 * 64;   // co + 8
                *(float2*)&out[o1] = make_float2(d[2], d[3]);
            }
    }
}

// ---------------------------------------------------------------------------
extern "C" void kernel_launch(void* const* d_in, const int* in_sizes, int n_in,
                              void* d_out, int out_size) {
    const float* x  = (const float*)d_in[0];
    const float* g  = (const float*)d_in[1];
    const float* w  = (const float*)d_in[2];
    const float* dw = (const float*)d_in[3];
    const float* db = (const float*)d_in[4];
    float* out = (float*)d_out;

    xT_kernel<<<dim3(64, 32), 256>>>(x);
    agg16_kernel<<<1024, 256>>>(w, g, dw, db);

    cudaFuncSetAttribute(conv_kernel,
                         cudaFuncAttributeMaxDynamicSharedMemorySize, SMEM_CONV);
    conv_kernel<<<dim3(16, 2, 32), 512, SMEM_CONV>>>(out);
}

// round 8
// speedup vs baseline: 1.2198x; 1.2198x over previous
#include <cuda_runtime.h>
#include <cuda_fp16.h>
#include <cstdint>

#define TEMP 30.0f

// ---------------- static device scratch ----------------
// aggregated fp16 weights, 48B-padded rows, stage-contiguous:
// [b][coH(2)][chunk(16)] { [tap(9)][coL(128)] rows of 48B (16 halfs + pad) }
__device__ __align__(16) __half g_w16[(size_t)32 * 2 * 16 * 9 * 128 * 24];
// transposed fp16 x, 48B-padded rows: [b][chunk(16)][f(64)][t(64)] rows of 48B
__device__ __align__(16) __half g_xT[(size_t)32 * 16 * 64 * 64 * 24];

// ---------------- helpers ----------------
__device__ __forceinline__ uint32_t smem_u32(const void* p) {
    uint32_t a;
    asm("{ .reg .u64 t; cvta.to.shared.u64 t, %1; cvt.u32.u64 %0, t; }" : "=r"(a) : "l"(p));
    return a;
}
__device__ __forceinline__ void ldsm_x4(uint32_t addr, uint32_t* r) {
    asm volatile("ldmatrix.sync.aligned.m8n8.x4.shared.b16 {%0,%1,%2,%3}, [%4];"
                 : "=r"(r[0]), "=r"(r[1]), "=r"(r[2]), "=r"(r[3]) : "r"(addr));
}
__device__ __forceinline__ void mma16816(float* d, const uint32_t* a,
                                         const uint32_t* b) {
    asm volatile(
        "mma.sync.aligned.m16n8k16.row.col.f32.f16.f16.f32 "
        "{%0,%1,%2,%3}, {%4,%5,%6,%7}, {%8,%9}, {%0,%1,%2,%3};"
        : "+f"(d[0]), "+f"(d[1]), "+f"(d[2]), "+f"(d[3])
        : "r"(a[0]), "r"(a[1]), "r"(a[2]), "r"(a[3]), "r"(b[0]), "r"(b[1]));
}
__device__ __forceinline__ void bulk_cp(uint32_t dst, const void* src,
                                        uint32_t bytes, uint32_t mbar) {
    asm volatile(
        "cp.async.bulk.shared::cluster.global.mbarrier::complete_tx::bytes "
        "[%0], [%1], %2, [%3];"
        :: "r"(dst), "l"(src), "r"(bytes), "r"(mbar) : "memory");
}
__device__ __forceinline__ void mbar_wait(uint32_t mb, uint32_t parity) {
    asm volatile(
        "{\n .reg .pred P1;\n"
        "W%=:\n mbarrier.try_wait.parity.acquire.cta.shared::cta.b64 P1, [%0], %1, 0x989680;\n"
        "@P1 bra D%=;\n bra W%=;\n D%=:\n}"
        :: "r"(mb), "r"(parity) : "memory");
}

// ---------------------------------------------------------------------------
// Kernel 1: aggregate expert weights -> fp16 padded layout (attention fused).
// ---------------------------------------------------------------------------
__global__ void agg16_kernel(const float* __restrict__ w,
                             const float* __restrict__ g,
                             const float* __restrict__ dw,
                             const float* __restrict__ db) {
    __shared__ float sp[4][4];
    __shared__ float s_att[4];
    const int b = blockIdx.x >> 5;
    const int tid = threadIdx.x;
    if (tid < 128) {
        int k = tid & 3, wrp = tid >> 5, lane = tid & 31;
        const float* gb = g + b * 256;
        float s = 0.f;
        for (int c = tid >> 2; c < 256; c += 32) s += gb[c] * dw[c * 4 + k];
        s += __shfl_xor_sync(~0u, s, 4);
        s += __shfl_xor_sync(~0u, s, 8);
        s += __shfl_xor_sync(~0u, s, 16);
        if (lane < 4) sp[wrp][k] = s;
    }
    __syncthreads();
    if (tid < 4) {
        int k = tid;
        float t = (sp[0][k] + sp[1][k] + sp[2][k] + sp[3][k] + db[k]) * (1.f / TEMP);
        float m = t;
        m = fmaxf(m, __shfl_xor_sync(0xF, m, 1));
        m = fmaxf(m, __shfl_xor_sync(0xF, m, 2));
        float e = expf(t - m);
        float su = e;
        su += __shfl_xor_sync(0xF, su, 1);
        su += __shfl_xor_sync(0xF, su, 2);
        s_att[k] = e / su;
    }
    __syncthreads();

    const int idx = blockIdx.x * 256 + tid;
    const int ci8 = idx & 31;
    const int co  = (idx >> 5) & 255;
    float acc[72];
#pragma unroll
    for (int e = 0; e < 72; ++e) acc[e] = 0.f;
#pragma unroll
    for (int k = 0; k < 4; ++k) {
        float a = s_att[k];
        const float4* wp =
            (const float4*)(w + (((size_t)k * 256 + co) * 256 + ci8 * 8) * 9);
#pragma unroll
        for (int q = 0; q < 18; ++q) {
            float4 f = wp[q];
            acc[q * 4 + 0] += a * f.x;
            acc[q * 4 + 1] += a * f.y;
            acc[q * 4 + 2] += a * f.z;
            acc[q * 4 + 3] += a * f.w;
        }
    }
    int coH = co >> 7, coL = co & 127, ch = ci8 >> 1, half8 = ci8 & 1;
#pragma unroll
    for (int kk = 0; kk < 9; ++kk) {
        __half2 h[4];
#pragma unroll
        for (int p = 0; p < 4; ++p)
            h[p] = __halves2half2(__float2half_rn(acc[(2 * p) * 9 + kk]),
                                  __float2half_rn(acc[(2 * p + 1) * 9 + kk]));
        __half* dst = g_w16 +
            (size_t)((((b * 2 + coH) * 16 + ch) * 9 + kk) * 128 + coL) * 24 + half8 * 8;
        *(uint4*)dst = *(uint4*)h;
    }
}

// ---------------------------------------------------------------------------
// Kernel 2: x -> fp16 transposed padded layout [b][chunk][f][t]·48B rows
// ---------------------------------------------------------------------------
__global__ void xT_kernel(const float* __restrict__ x) {
    __shared__ __half s[64][272];
    int f = blockIdx.x, b = blockIdx.y, tid = threadIdx.x;
    const float* xb = x + ((size_t)b * 256 * 4096 + (size_t)f * 64);
    for (int i = tid; i < 256 * 64; i += 256) {
        int ci = i >> 6, t = i & 63;
        s[t][ci] = __float2half_rn(xb[(size_t)ci * 4096 + t]);
    }
    __syncthreads();
#pragma unroll
    for (int it = 0; it < 8; ++it) {
        int i = it * 256 + tid;              // 2048 uint4 writes
        int ch = i >> 7, rem = i & 127;
        int t = rem >> 1, q = rem & 1;
        __half* dst = g_xT +
            (size_t)(((b * 16 + ch) * 64 + f) * 64 + t) * 24 + q * 8;
        *(uint4*)dst = *(uint4*)&s[t][ch * 16 + q * 8];
    }
}

// ---------------------------------------------------------------------------
// Kernel 3: conv via mma.sync m16n8k16 + cp.async.bulk stage loads.
// CTA = (b, coH 128co, 4 fo x 64 t), 256 threads / 8 warps.
// Warp tile 64co x 64t x 1fo: wco=wid&1, wfo=wid>>1. 3-stage pipeline.
// ---------------------------------------------------------------------------
#define STG_A 55296          // 9 taps * 128 co * 48B, one contiguous bulk copy
#define STG_B 19008          // 6 fi planes * 66 t-rows * 48B
#define NSTG 3
#define B_BASE (NSTG * STG_A)
#define SMEM_CONV (NSTG * STG_A + NSTG * STG_B)   // 222912

__global__ __launch_bounds__(256, 1) void conv_kernel(float* __restrict__ out) {
    extern __shared__ __align__(16) char smem[];
    __shared__ __align__(8) uint64_t s_mb[NSTG];
    const int tid = threadIdx.x, wid = tid >> 5, lane = tid & 31;
    const int b = blockIdx.z, coH = blockIdx.y, fo0 = blockIdx.x * 4;
    const int wco = wid & 1, wfo = wid >> 1;
    const uint32_t sb = smem_u32(smem);
    uint32_t mb[NSTG];
#pragma unroll
    for (int i = 0; i < NSTG; ++i) mb[i] = smem_u32(&s_mb[i]);

    // zero all B stages (halo rows/planes stay zero forever)
    for (int i = tid; i < NSTG * STG_B / 4; i += 256)
        ((uint32_t*)(smem + B_BASE))[i] = 0u;
    if (tid == 0) {
#pragma unroll
        for (int i = 0; i < NSTG; ++i)
            asm volatile("mbarrier.init.shared.b64 [%0], 1;" :: "r"(mb[i]) : "memory");
    }
    __syncthreads();

    const __half* wbase = g_w16 + (size_t)((b * 2 + coH) * 16) * (9 * 128 * 24);
    const int pLo = (fo0 == 0) ? 1 : 0;
    const int pHi = (fo0 == 60) ? 5 : 6;
    const uint32_t txBytes = STG_A + (uint32_t)(pHi - pLo) * 3072u;

    auto load_stage = [&](int ch) {
        const int slot = ch % NSTG;
        const uint32_t st = sb + slot * STG_A;
        asm volatile("mbarrier.arrive.expect_tx.shared.b64 _, [%0], %1;"
                     :: "r"(mb[slot]), "r"(txBytes) : "memory");
        bulk_cp(st, wbase + (size_t)ch * (9 * 128 * 24), STG_A, mb[slot]);
        const uint32_t bd = sb + B_BASE + slot * STG_B;
        for (int p = pLo; p < pHi; ++p) {
            int fi = fo0 - 1 + p;
            bulk_cp(bd + p * 3168 + 48,
                    g_xT + (size_t)(((b * 16 + ch) * 64 + fi) * 64) * 24,
                    3072u, mb[slot]);
        }
    };

    float acc[4][8][4];
#pragma unroll
    for (int m = 0; m < 4; ++m)
#pragma unroll
        for (int n = 0; n < 8; ++n)
#pragma unroll
            for (int e = 0; e < 4; ++e) acc[m][n][e] = 0.f;

    if (tid == 0) {
        load_stage(0);
        load_stage(1);
        load_stage(2);
    }

    const uint32_t aLane = (lane & 15) * 48 + (lane >> 4) * 16;
    const uint32_t bLane = ((lane & 7) + ((lane & 16) >> 1)) * 48 +
                           ((lane & 8) ? 16u : 0u);

    for (int ch = 0; ch < 16; ++ch) {
        const int slot = ch % NSTG;
        mbar_wait(mb[slot], (ch / NSTG) & 1);

        const uint32_t As = sb + slot * STG_A + (wco * 64) * 48 + aLane;
        const uint32_t Bs = sb + B_BASE + slot * STG_B + (wfo * 3168) + bLane;
#pragma unroll
        for (int kh = 0; kh < 3; ++kh) {
#pragma unroll
            for (int kw = 0; kw < 3; ++kw) {
                const int tap = kh * 3 + kw;
                uint32_t a[4][4];
#pragma unroll
                for (int m = 0; m < 4; ++m)
                    ldsm_x4(As + tap * 6144 + m * 768, a[m]);
                uint32_t bf[4][4];
                const uint32_t Bp = Bs + kh * 3168 + kw * 48;
#pragma unroll
                for (int nt = 0; nt < 4; ++nt)
                    ldsm_x4(Bp + nt * 768, bf[nt]);
#pragma unroll
                for (int m = 0; m < 4; ++m)
#pragma unroll
                    for (int nt = 0; nt < 4; ++nt) {
                        mma16816(acc[m][nt * 2],     a[m], bf[nt]);
                        mma16816(acc[m][nt * 2 + 1], a[m], bf[nt] + 2);
                    }
            }
        }
        __syncthreads();
        if (tid == 0 && ch + 3 < 16) load_stage(ch + 3);
    }

    // epilogue: direct float2 stores
    const int gRow = lane >> 2, col2 = (lane & 3) * 2;
    const int fo = fo0 + wfo;
#pragma unroll
    for (int m = 0; m < 4; ++m) {
        const int co = coH * 128 + wco * 64 + m * 16 + gRow;
#pragma unroll
        for (int nt = 0; nt < 4; ++nt)
#pragma unroll
            for (int j = 0; j < 2; ++j) {
                const int t = nt * 16 + j * 8 + col2;
                const float* d = acc[m][nt * 2 + j];
                size_t o0 = (((size_t)(b * 256 + co)) * 64 + fo) * 64 + t;
                *(float2*)&out[o0] = make_float2(d[0], d[1]);
                size_t o1 = o0 + 8 * 64 * 64;   // co + 8
                *(float2*)&out[o1] = make_float2(d[2], d[3]);
            }
    }
}

// ---------------------------------------------------------------------------
extern "C" void kernel_launch(void* const* d_in, const int* in_sizes, int n_in,
                              void* d_out, int out_size) {
    const float* x  = (const float*)d_in[0];
    const float* g  = (const float*)d_in[1];
    const float* w  = (const float*)d_in[2];
    const float* dw = (const float*)d_in[3];
    const float* db = (const float*)d_in[4];
    float* out = (float*)d_out;

    xT_kernel<<<dim3(64, 32), 256>>>(x);
    agg16_kernel<<<1024, 256>>>(w, g, dw, db);

    cudaFuncSetAttribute(conv_kernel,
                         cudaFuncAttributeMaxDynamicSharedMemorySize, SMEM_CONV);
    conv_kernel<<<dim3(16, 2, 32), 256, SMEM_CONV>>>(out);
}

// round 9
// speedup vs baseline: 1.2303x; 1.0086x over previous
#include <cuda_runtime.h>
#include <cuda_fp16.h>
#include <cstdint>

#define TEMP 30.0f

// ---------------- static device scratch ----------------
// aggregated fp16 weights, 48B-padded rows, stage-contiguous:
// [b][coH(2)][chunk(16)] { [tap(9)][coL(128)] rows of 48B (16 halfs + pad) }
__device__ __align__(16) __half g_w16[(size_t)32 * 2 * 16 * 9 * 128 * 24];
// transposed fp16 x, 48B-padded rows: [b][chunk(16)][f(64)][t(64)] rows of 48B
__device__ __align__(16) __half g_xT[(size_t)32 * 16 * 64 * 64 * 24];

// ---------------- helpers ----------------
__device__ __forceinline__ uint32_t smem_u32(const void* p) {
    uint32_t a;
    asm("{ .reg .u64 t; cvta.to.shared.u64 t, %1; cvt.u32.u64 %0, t; }" : "=r"(a) : "l"(p));
    return a;
}
__device__ __forceinline__ void ldsm_x4(uint32_t addr, uint32_t* r) {
    asm volatile("ldmatrix.sync.aligned.m8n8.x4.shared.b16 {%0,%1,%2,%3}, [%4];"
                 : "=r"(r[0]), "=r"(r[1]), "=r"(r[2]), "=r"(r[3]) : "r"(addr));
}
__device__ __forceinline__ void mma16816(float* d, const uint32_t* a,
                                         const uint32_t* b) {
    asm volatile(
        "mma.sync.aligned.m16n8k16.row.col.f32.f16.f16.f32 "
        "{%0,%1,%2,%3}, {%4,%5,%6,%7}, {%8,%9}, {%0,%1,%2,%3};"
        : "+f"(d[0]), "+f"(d[1]), "+f"(d[2]), "+f"(d[3])
        : "r"(a[0]), "r"(a[1]), "r"(a[2]), "r"(a[3]), "r"(b[0]), "r"(b[1]));
}
__device__ __forceinline__ void bulk_cp(uint32_t dst, const void* src,
                                        uint32_t bytes, uint32_t mbar) {
    asm volatile(
        "cp.async.bulk.shared::cluster.global.mbarrier::complete_tx::bytes "
        "[%0], [%1], %2, [%3];"
        :: "r"(dst), "l"(src), "r"(bytes), "r"(mbar) : "memory");
}
__device__ __forceinline__ void mbar_wait(uint32_t mb, uint32_t parity) {
    asm volatile(
        "{\n .reg .pred P1;\n"
        "W%=:\n mbarrier.try_wait.parity.acquire.cta.shared::cta.b64 P1, [%0], %1, 0x989680;\n"
        "@P1 bra D%=;\n bra W%=;\n D%=:\n}"
        :: "r"(mb), "r"(parity) : "memory");
}

// ---------------------------------------------------------------------------
// Kernel 1: aggregate expert weights -> fp16 padded layout (attention fused).
// ---------------------------------------------------------------------------
__global__ void agg16_kernel(const float* __restrict__ w,
                             const float* __restrict__ g,
                             const float* __restrict__ dw,
                             const float* __restrict__ db) {
    __shared__ float sp[4][4];
    __shared__ float s_att[4];
    const int b = blockIdx.x >> 5;
    const int tid = threadIdx.x;
    if (tid < 128) {
        int k = tid & 3, wrp = tid >> 5, lane = tid & 31;
        const float* gb = g + b * 256;
        float s = 0.f;
        for (int c = tid >> 2; c < 256; c += 32) s += gb[c] * dw[c * 4 + k];
        s += __shfl_xor_sync(~0u, s, 4);
        s += __shfl_xor_sync(~0u, s, 8);
        s += __shfl_xor_sync(~0u, s, 16);
        if (lane < 4) sp[wrp][k] = s;
    }
    __syncthreads();
    if (tid < 4) {
        int k = tid;
        float t = (sp[0][k] + sp[1][k] + sp[2][k] + sp[3][k] + db[k]) * (1.f / TEMP);
        float m = t;
        m = fmaxf(m, __shfl_xor_sync(0xF, m, 1));
        m = fmaxf(m, __shfl_xor_sync(0xF, m, 2));
        float e = expf(t - m);
        float su = e;
        su += __shfl_xor_sync(0xF, su, 1);
        su += __shfl_xor_sync(0xF, su, 2);
        s_att[k] = e / su;
    }
    __syncthreads();

    const int idx = blockIdx.x * 256 + tid;
    const int ci8 = idx & 31;
    const int co  = (idx >> 5) & 255;
    float acc[72];
#pragma unroll
    for (int e = 0; e < 72; ++e) acc[e] = 0.f;
#pragma unroll
    for (int k = 0; k < 4; ++k) {
        float a = s_att[k];
        const float4* wp =
            (const float4*)(w + (((size_t)k * 256 + co) * 256 + ci8 * 8) * 9);
#pragma unroll
        for (int q = 0; q < 18; ++q) {
            float4 f = wp[q];
            acc[q * 4 + 0] += a * f.x;
            acc[q * 4 + 1] += a * f.y;
            acc[q * 4 + 2] += a * f.z;
            acc[q * 4 + 3] += a * f.w;
        }
    }
    int coH = co >> 7, coL = co & 127, ch = ci8 >> 1, half8 = ci8 & 1;
#pragma unroll
    for (int kk = 0; kk < 9; ++kk) {
        __half2 h[4];
#pragma unroll
        for (int p = 0; p < 4; ++p)
            h[p] = __halves2half2(__float2half_rn(acc[(2 * p) * 9 + kk]),
                                  __float2half_rn(acc[(2 * p + 1) * 9 + kk]));
        __half* dst = g_w16 +
            (size_t)((((b * 2 + coH) * 16 + ch) * 9 + kk) * 128 + coL) * 24 + half8 * 8;
        *(uint4*)dst = *(uint4*)h;
    }
}

// ---------------------------------------------------------------------------
// Kernel 2: x -> fp16 transposed padded layout [b][chunk][f][t]·48B rows.
// smem row = 276 halfs (138 words): 2-way conflicts instead of 8-way.
// ---------------------------------------------------------------------------
__global__ void xT_kernel(const float* __restrict__ x) {
    __shared__ __half s[64][276];
    int f = blockIdx.x, b = blockIdx.y, tid = threadIdx.x;
    const float* xb = x + ((size_t)b * 256 * 4096 + (size_t)f * 64);
    for (int i = tid; i < 256 * 64; i += 256) {
        int ci = i >> 6, t = i & 63;
        s[t][ci] = __float2half_rn(xb[(size_t)ci * 4096 + t]);
    }
    __syncthreads();
#pragma unroll
    for (int it = 0; it < 8; ++it) {
        int i = it * 256 + tid;              // 2048 units
        int ch = i >> 7, rem = i & 127;
        int t = rem >> 1, q = rem & 1;
        const __half* sp2 = &s[t][ch * 16 + q * 8];
        uint2 lo = *(const uint2*)sp2;       // 8B-aligned (552t + 32ch + 16q)
        uint2 hi = *(const uint2*)(sp2 + 4);
        uint4 o = make_uint4(lo.x, lo.y, hi.x, hi.y);
        __half* dst = g_xT +
            (size_t)(((b * 16 + ch) * 64 + f) * 64 + t) * 24 + q * 8;
        *(uint4*)dst = o;
    }
}

// ---------------------------------------------------------------------------
// Kernel 3: conv via mma.sync m16n8k16 + cp.async.bulk stage loads.
// CTA = (b, coH 128co, 4 fo x 64 t), 256 threads / 8 warps.
// Warp tile 64co x 64t x 1fo. 3-stage pipeline. Tap-level fragment
// double-buffering: prefetch tap+1 LDSMs while tap's MMAs issue.
// ---------------------------------------------------------------------------
#define STG_A 55296          // 9 taps * 128 co * 48B, one contiguous bulk copy
#define STG_B 19008          // 6 fi planes * 66 t-rows * 48B
#define NSTG 3
#define B_BASE (NSTG * STG_A)
#define SMEM_CONV (NSTG * STG_A + NSTG * STG_B)   // 222912

__global__ __launch_bounds__(256, 1) void conv_kernel(float* __restrict__ out) {
    extern __shared__ __align__(16) char smem[];
    __shared__ __align__(8) uint64_t s_mb[NSTG];
    const int tid = threadIdx.x, wid = tid >> 5, lane = tid & 31;
    const int b = blockIdx.z, coH = blockIdx.y, fo0 = blockIdx.x * 4;
    const int wco = wid & 1, wfo = wid >> 1;
    const uint32_t sb = smem_u32(smem);
    uint32_t mb[NSTG];
#pragma unroll
    for (int i = 0; i < NSTG; ++i) mb[i] = smem_u32(&s_mb[i]);

    // zero all B stages (halo rows/planes stay zero forever)
    for (int i = tid; i < NSTG * STG_B / 4; i += 256)
        ((uint32_t*)(smem + B_BASE))[i] = 0u;
    if (tid == 0) {
#pragma unroll
        for (int i = 0; i < NSTG; ++i)
            asm volatile("mbarrier.init.shared.b64 [%0], 1;" :: "r"(mb[i]) : "memory");
    }
    __syncthreads();

    const __half* wbase = g_w16 + (size_t)((b * 2 + coH) * 16) * (9 * 128 * 24);
    const int pLo = (fo0 == 0) ? 1 : 0;
    const int pHi = (fo0 == 60) ? 5 : 6;
    const uint32_t txBytes = STG_A + (uint32_t)(pHi - pLo) * 3072u;

    auto load_stage = [&](int ch) {
        const int slot = ch % NSTG;
        const uint32_t st = sb + slot * STG_A;
        asm volatile("mbarrier.arrive.expect_tx.shared.b64 _, [%0], %1;"
                     :: "r"(mb[slot]), "r"(txBytes) : "memory");
        bulk_cp(st, wbase + (size_t)ch * (9 * 128 * 24), STG_A, mb[slot]);
        const uint32_t bd = sb + B_BASE + slot * STG_B;
        for (int p = pLo; p < pHi; ++p) {
            int fi = fo0 - 1 + p;
            bulk_cp(bd + p * 3168 + 48,
                    g_xT + (size_t)(((b * 16 + ch) * 64 + fi) * 64) * 24,
                    3072u, mb[slot]);
        }
    };

    float acc[4][8][4];
#pragma unroll
    for (int m = 0; m < 4; ++m)
#pragma unroll
        for (int n = 0; n < 8; ++n)
#pragma unroll
            for (int e = 0; e < 4; ++e) acc[m][n][e] = 0.f;

    if (tid == 0) {
        load_stage(0);
        load_stage(1);
        load_stage(2);
    }

    const uint32_t aLane = (lane & 15) * 48 + (lane >> 4) * 16;
    const uint32_t bLane = ((lane & 7) + ((lane & 16) >> 1)) * 48 +
                           ((lane & 8) ? 16u : 0u);

    for (int ch = 0; ch < 16; ++ch) {
        const int slot = ch % NSTG;
        mbar_wait(mb[slot], (ch / NSTG) & 1);

        const uint32_t As = sb + slot * STG_A + (wco * 64) * 48 + aLane;
        const uint32_t Bs = sb + B_BASE + slot * STG_B + (wfo * 3168) + bLane;

        auto ldA = [&](uint32_t (&a)[4][4], int tap) {
#pragma unroll
            for (int m = 0; m < 4; ++m)
                ldsm_x4(As + tap * 6144 + m * 768, a[m]);
        };
        auto ldB = [&](uint32_t (&bf)[4][4], int tap) {
            const int kh = tap / 3, kw = tap - kh * 3;
            const uint32_t Bp = Bs + kh * 3168 + kw * 48;
#pragma unroll
            for (int nt = 0; nt < 4; ++nt)
                ldsm_x4(Bp + nt * 768, bf[nt]);
        };
        auto domma = [&](uint32_t (&a)[4][4], uint32_t (&bf)[4][4]) {
#pragma unroll
            for (int m = 0; m < 4; ++m)
#pragma unroll
                for (int nt = 0; nt < 4; ++nt) {
                    mma16816(acc[m][nt * 2],     a[m], bf[nt]);
                    mma16816(acc[m][nt * 2 + 1], a[m], bf[nt] + 2);
                }
        };

        uint32_t aB[2][4][4], bB[2][4][4];
        ldA(aB[0], 0);
        ldB(bB[0], 0);
#pragma unroll
        for (int tap = 0; tap < 9; ++tap) {
            const int cur = tap & 1, nxt = cur ^ 1;
            if (tap < 8) {
                ldA(aB[nxt], tap + 1);
                ldB(bB[nxt], tap + 1);
            }
            domma(aB[cur], bB[cur]);
        }

        __syncthreads();
        if (tid == 0 && ch + 3 < 16) load_stage(ch + 3);
    }

    // epilogue: direct float2 stores
    const int gRow = lane >> 2, col2 = (lane & 3) * 2;
    const int fo = fo0 + wfo;
#pragma unroll
    for (int m = 0; m < 4; ++m) {
        const int co = coH * 128 + wco * 64 + m * 16 + gRow;
#pragma unroll
        for (int nt = 0; nt < 4; ++nt)
#pragma unroll
            for (int j = 0; j < 2; ++j) {
                const int t = nt * 16 + j * 8 + col2;
                const float* d = acc[m][nt * 2 + j];
                size_t o0 = (((size_t)(b * 256 + co)) * 64 + fo) * 64 + t;
                *(float2*)&out[o0] = make_float2(d[0], d[1]);
                size_t o1 = o0 + 8 * 64 * 64;   // co + 8
                *(float2*)&out[o1] = make_float2(d[2], d[3]);
            }
    }
}

// ---------------------------------------------------------------------------
extern "C" void kernel_launch(void* const* d_in, const int* in_sizes, int n_in,
                              void* d_out, int out_size) {
    const float* x  = (const float*)d_in[0];
    const float* g  = (const float*)d_in[1];
    const float* w  = (const float*)d_in[2];
    const float* dw = (const float*)d_in[3];
    const float* db = (const float*)d_in[4];
    float* out = (float*)d_out;

    xT_kernel<<<dim3(64, 32), 256>>>(x);
    agg16_kernel<<<1024, 256>>>(w, g, dw, db);

    cudaFuncSetAttribute(conv_kernel,
                         cudaFuncAttributeMaxDynamicSharedMemorySize, SMEM_CONV);
    conv_kernel<<<dim3(16, 2, 32), 256, SMEM_CONV>>>(out);
}